// round 9
// baseline (speedup 1.0000x reference)
#include <cuda_runtime.h>
#include <cstdint>
#include <math.h>

// ---------------------------------------------------------------------------
// A: register-streaming pool + circuit closed form (no staging smem)
//    warp = 8 images; lane = (img, quarter q). Thread loads 9 float4 (its 36
//    contiguous floats of the image's first 144), accumulates 4 group sums
//    with static mapping, butterfly-shfl across the 4 lanes of the image.
// S: 1-block stats finalize -> g_sb.   C: pure normalize (1 float4/thread).
// ---------------------------------------------------------------------------

#define B_TOTAL 65536
#define IPB     64                      // images per block (8 warps x 8 images)
#define NB      (B_TOTAL / IPB)         // 1024 blocks
#define THREADS 256

__device__ __align__(16) float g_part[NB * 8];  // per-block [sum0..3, sumsq0..3]
__device__ __align__(16) float g_sb[8];         // scale[4], bias[4]

// group-of-column map for float4 p (0..8 within a thread's 9, base c0 = (4p)%24)
// element groups per c0: 0:{0000} 4:{0011} 8:{1111} 12:{2222} 16:{2233} 20:{3333}

__global__ __launch_bounds__(THREADS, 6)
void qfc_kernelA(const float* __restrict__ x,
                 const float* __restrict__ pr,
                 float* __restrict__ out)
{
    __shared__ float sz[IPB][4];
    __shared__ float swarp[8][8];

    const int tid  = threadIdx.x;
    const int wid  = tid >> 5;
    const int lane = tid & 31;
    const int q    = lane & 3;          // quarter within image
    const int imw  = lane >> 2;         // image within warp (0..7)
    const int img  = wid * 8 + imw;     // image within block (0..63)
    const long gimg = (long)blockIdx.x * IPB + img;

    const float4* __restrict__ x4 = (const float4*)x;
    const long base = gimg * 144 + q * 9;   // thread's 9 float4

    // ---- load 9 float4, accumulate into 4 group sums (static mapping) ------
    float s0 = 0.f, s1 = 0.f, s2 = 0.f, s3 = 0.f;
#pragma unroll
    for (int p = 0; p < 9; p++) {
        float4 v = __ldg(&x4[base + p]);
        const int c0 = (4 * (p /*within thread*/ ) + q * 36) % 24;  // column of v.x
        // c0 is compile-time per (p) only if q*36%24 folds: q*36 %24 = (q%2)*12
        // handle via two static cases on (q&1) to keep mapping static:
        if (((q & 1) == 0)) {
            // c0 cycles 0,4,8,12,16,20 starting at 0 for p=0
            switch (p % 6) {
                case 0: s0 += v.x + v.y + v.z + v.w; break;
                case 1: s0 += v.x + v.y; s1 += v.z + v.w; break;
                case 2: s1 += v.x + v.y + v.z + v.w; break;
                case 3: s2 += v.x + v.y + v.z + v.w; break;
                case 4: s2 += v.x + v.y; s3 += v.z + v.w; break;
                default: s3 += v.x + v.y + v.z + v.w; break;
            }
        } else {
            // q odd: column base shifted by 12
            switch (p % 6) {
                case 0: s2 += v.x + v.y + v.z + v.w; break;
                case 1: s2 += v.x + v.y; s3 += v.z + v.w; break;
                case 2: s3 += v.x + v.y + v.z + v.w; break;
                case 3: s0 += v.x + v.y + v.z + v.w; break;
                case 4: s0 += v.x + v.y; s1 += v.z + v.w; break;
                default: s1 += v.x + v.y + v.z + v.w; break;
            }
        }
    }

    // ---- butterfly across the 4 lanes of this image -----------------------
#pragma unroll
    for (int m = 1; m <= 2; m <<= 1) {
        s0 += __shfl_xor_sync(0xffffffffu, s0, m);
        s1 += __shfl_xor_sync(0xffffffffu, s1, m);
        s2 += __shfl_xor_sync(0xffffffffu, s2, m);
        s3 += __shfl_xor_sync(0xffffffffu, s3, m);
    }

    // this lane handles group g = q
    const float sg   = (q == 0) ? s0 : (q == 1) ? s1 : (q == 2) ? s2 : s3;
    const float phi  = pr[q * 2 + 0];
    const float lam  = pr[q * 2 + 1];
    const float theta = sg * (1.f / 36.f);
    float st, ct;
    __sincosf(theta, &st, &ct);
    const float z = __cosf(lam) * ct + __sinf(lam) * __sinf(phi) * st;
    sz[img][q] = z;
    __syncwarp();

    // ---- q==0 lane: products, coalesced write, stat accumulation ----------
    float acc[8] = {0.f, 0.f, 0.f, 0.f, 0.f, 0.f, 0.f, 0.f};
    if (q == 0) {
        float4 zz = *(float4*)&sz[img][0];
        float o0 = zz.x;
        float o1 = o0 * zz.y;
        float o2 = o1 * zz.z;
        float o3 = o2 * zz.w;
        ((float4*)out)[gimg] = make_float4(o0, o1, o2, o3);
        acc[0] = o0;      acc[1] = o1;      acc[2] = o2;      acc[3] = o3;
        acc[4] = o0 * o0; acc[5] = o1 * o1; acc[6] = o2 * o2; acc[7] = o3 * o3;
    }

    // warp reduction (zeros elsewhere), then cross-warp combine
#pragma unroll
    for (int k = 0; k < 8; k++) {
#pragma unroll
        for (int off = 16; off >= 4; off >>= 1)
            acc[k] += __shfl_down_sync(0xffffffffu, acc[k], off);
    }
    if (lane == 0) {
#pragma unroll
        for (int k = 0; k < 8; k++) swarp[wid][k] = acc[k];
    }
    __syncthreads();
    if (tid < 8) {
        float r = 0.f;
#pragma unroll
        for (int w = 0; w < 8; w++) r += swarp[w][tid];
        g_part[blockIdx.x * 8 + tid] = r;
    }
}

// ---- S: single-block stats finalize -> g_sb --------------------------------
__global__ __launch_bounds__(256)
void qfc_kernelS(const float* __restrict__ gamma,
                 const float* __restrict__ beta)
{
    __shared__ float swarp[8][8];
    const int tid  = threadIdx.x;
    const int wrp  = tid >> 5;
    const int lane = tid & 31;

    const float4* __restrict__ p4 = (const float4*)g_part;   // 2048 float4
    float r[8] = {0.f, 0.f, 0.f, 0.f, 0.f, 0.f, 0.f, 0.f};
#pragma unroll
    for (int it = 0; it < NB / 256; it++) {                   // 4 iters
        int j = tid + it * 256;
        float4 s = __ldcg(&p4[j * 2]);
        float4 qq = __ldcg(&p4[j * 2 + 1]);
        r[0] += s.x; r[1] += s.y; r[2] += s.z; r[3] += s.w;
        r[4] += qq.x; r[5] += qq.y; r[6] += qq.z; r[7] += qq.w;
    }
#pragma unroll
    for (int k = 0; k < 8; k++) {
#pragma unroll
        for (int off = 16; off; off >>= 1)
            r[k] += __shfl_down_sync(0xffffffffu, r[k], off);
    }
    if (lane == 0) {
#pragma unroll
        for (int k = 0; k < 8; k++) swarp[wrp][k] = r[k];
    }
    __syncthreads();

    if (tid < 4) {
        float ss = 0.f, qq = 0.f;
#pragma unroll
        for (int w = 0; w < 8; w++) { ss += swarp[w][tid]; qq += swarp[w][4 + tid]; }
        const float mean = ss * (1.f / (float)B_TOTAL);
        const float ex2  = qq * (1.f / (float)B_TOTAL);
        const float var  = fmaxf(ex2 - mean * mean, 0.f);
        const float inv  = rsqrtf(var + 1e-5f);
        const float sc   = gamma[tid] * inv;
        g_sb[tid]     = sc;
        g_sb[4 + tid] = beta[tid] - mean * sc;
    }
}

// ---- C: pure normalize, 1 float4 per thread --------------------------------
__global__ __launch_bounds__(256)
void qfc_kernelC(float* __restrict__ out)
{
    const float4 scv = *(const float4*)&g_sb[0];
    const float4 biv = *(const float4*)&g_sb[4];
    const int i = blockIdx.x * 256 + threadIdx.x;    // 65536 threads total
    float4 v = ((float4*)out)[i];
    v.x = v.x * scv.x + biv.x;
    v.y = v.y * scv.y + biv.y;
    v.z = v.z * scv.z + biv.z;
    v.w = v.w * scv.w + biv.w;
    ((float4*)out)[i] = v;
}

extern "C" void kernel_launch(void* const* d_in, const int* in_sizes, int n_in,
                              void* d_out, int out_size)
{
    const float* x      = (const float*)d_in[0];   // [65536,1,24,24]
    const float* params = (const float*)d_in[1];   // [4,2]
    const float* gamma  = (const float*)d_in[2];   // [4]
    const float* beta   = (const float*)d_in[3];   // [4]
    float* out = (float*)d_out;                    // [65536,4]

    qfc_kernelA<<<NB, THREADS>>>(x, params, out);
    qfc_kernelS<<<1, 256>>>(gamma, beta);
    qfc_kernelC<<<B_TOTAL / 256, 256>>>(out);
}

// round 10
// speedup vs baseline: 1.1451x; 1.1451x over previous
#include <cuda_runtime.h>
#include <cstdint>
#include <math.h>

// ---------------------------------------------------------------------------
// A: cp.async staging, 64 images/block in 2 commit groups of 32; pooling +
//    circuit closed form; shfl-based cumulative products (no z smem).
// S: 1-block stats finalize -> g_sb.   C: pure normalize (1 float4/thread).
// ---------------------------------------------------------------------------

#define B_TOTAL 65536
#define IPB     64
#define NB      (B_TOTAL / IPB)         // 1024 blocks
#define THREADS 256
#define SROW    144                     // 6 rows x 24 cols, 16B-aligned rows

__device__ __align__(16) float g_part[NB * 8];  // per-block [sum0..3, sumsq0..3]
__device__ __align__(16) float g_sb[8];         // scale[4], bias[4]

__device__ __forceinline__ void cp16(unsigned int saddr, const float4* gptr) {
    asm volatile("cp.async.cg.shared.global [%0], [%1], 16;" :: "r"(saddr), "l"(gptr));
}

__global__ __launch_bounds__(THREADS, 6)
void qfc_kernelA(const float* __restrict__ x,
                 const float* __restrict__ pr,
                 float* __restrict__ out)
{
    __shared__ __align__(16) float sd[IPB][SROW];   // 36,864 B
    __shared__ float swarp[8][8];

    const int tid  = threadIdx.x;
    const int wid  = tid >> 5;
    const int lane = tid & 31;
    const int g    = tid & 3;           // group / qubit index
    const int img  = tid >> 2;          // image within block (0..63)
    const long ib  = (long)blockIdx.x * IPB;

    const float4* __restrict__ x4 = (const float4*)x;

    // ---- two commit groups: images [0,32) and [32,64), 1152 cp.async each --
#pragma unroll
    for (int h = 0; h < 2; h++) {
#pragma unroll
        for (int it = 0; it < 5; it++) {
            int i = tid + it * THREADS;
            if (i < 32 * 36) {
                int im = (i / 36) + 32 * h;
                int p  = i % 36;
                unsigned int sa =
                    (unsigned int)__cvta_generic_to_shared(&sd[im][p * 4]);
                cp16(sa, &x4[(ib + im) * 144 + p]);
            }
        }
        asm volatile("cp.async.commit_group;");
    }

    const float phi  = pr[g * 2 + 0];
    const float lam  = pr[g * 2 + 1];
    const float clam = __cosf(lam);
    const float k2   = __sinf(lam) * __sinf(phi);

    float myz = 0.f;

    // pooling + single-qubit z for this thread's (img, g)
    auto pool_z = [&]() {
        const float* row = &sd[img][g * 6];
        float a0 = 0.f, a1 = 0.f, a2 = 0.f, a3 = 0.f;
#pragma unroll
        for (int r = 0; r < 6; r++) {
            a0 += row[r * 24 + 0];
            a1 += row[r * 24 + 1];
            a2 += row[r * 24 + 2];
            a3 += row[r * 24 + 3];
            a0 += row[r * 24 + 4];
            a1 += row[r * 24 + 5];
        }
        const float theta = ((a0 + a1) + (a2 + a3)) * (1.f / 36.f);
        float st, ct;
        __sincosf(theta, &st, &ct);
        myz = clam * ct + k2 * st;
    };

    // ---- phase 0: group 0 ready, warps 0-3 (images 0..31) compute ----------
    asm volatile("cp.async.wait_group 1;");
    __syncthreads();
    if (tid < 128) pool_z();

    // ---- phase 1: group 1 ready, warps 4-7 (images 32..63) compute ---------
    asm volatile("cp.async.wait_group 0;");
    __syncthreads();
    if (tid >= 128) pool_z();

    // ---- shfl-gather the 4 z's of this image (adjacent lanes) --------------
    const unsigned base = lane & ~3u;
    const float z0 = __shfl_sync(0xffffffffu, myz, base + 0);
    const float z1 = __shfl_sync(0xffffffffu, myz, base + 1);
    const float z2 = __shfl_sync(0xffffffffu, myz, base + 2);
    const float z3 = __shfl_sync(0xffffffffu, myz, base + 3);

    float acc[8] = {0.f, 0.f, 0.f, 0.f, 0.f, 0.f, 0.f, 0.f};
    if (g == 0) {
        const float o0 = z0;
        const float o1 = o0 * z1;
        const float o2 = o1 * z2;
        const float o3 = o2 * z3;
        ((float4*)out)[ib + img] = make_float4(o0, o1, o2, o3);
        acc[0] = o0;      acc[1] = o1;      acc[2] = o2;      acc[3] = o3;
        acc[4] = o0 * o0; acc[5] = o1 * o1; acc[6] = o2 * o2; acc[7] = o3 * o3;
    }

    // warp reduction over lanes 0,4,..,28 (zeros elsewhere are inert)
#pragma unroll
    for (int k = 0; k < 8; k++) {
#pragma unroll
        for (int off = 16; off >= 4; off >>= 1)
            acc[k] += __shfl_down_sync(0xffffffffu, acc[k], off);
    }
    if (lane == 0) {
#pragma unroll
        for (int k = 0; k < 8; k++) swarp[wid][k] = acc[k];
    }
    __syncthreads();
    if (tid < 8) {
        float r = 0.f;
#pragma unroll
        for (int w = 0; w < 8; w++) r += swarp[w][tid];
        g_part[blockIdx.x * 8 + tid] = r;
    }
}

// ---- S: single-block stats finalize -> g_sb --------------------------------
__global__ __launch_bounds__(256)
void qfc_kernelS(const float* __restrict__ gamma,
                 const float* __restrict__ beta)
{
    __shared__ float swarp[8][8];
    const int tid  = threadIdx.x;
    const int wrp  = tid >> 5;
    const int lane = tid & 31;

    const float4* __restrict__ p4 = (const float4*)g_part;   // 2048 float4
    float r[8] = {0.f, 0.f, 0.f, 0.f, 0.f, 0.f, 0.f, 0.f};
#pragma unroll
    for (int it = 0; it < NB / 256; it++) {                   // 4 iters
        int j = tid + it * 256;
        float4 s  = __ldcg(&p4[j * 2]);
        float4 qq = __ldcg(&p4[j * 2 + 1]);
        r[0] += s.x;  r[1] += s.y;  r[2] += s.z;  r[3] += s.w;
        r[4] += qq.x; r[5] += qq.y; r[6] += qq.z; r[7] += qq.w;
    }
#pragma unroll
    for (int k = 0; k < 8; k++) {
#pragma unroll
        for (int off = 16; off; off >>= 1)
            r[k] += __shfl_down_sync(0xffffffffu, r[k], off);
    }
    if (lane == 0) {
#pragma unroll
        for (int k = 0; k < 8; k++) swarp[wrp][k] = r[k];
    }
    __syncthreads();

    if (tid < 4) {
        float ss = 0.f, qq = 0.f;
#pragma unroll
        for (int w = 0; w < 8; w++) { ss += swarp[w][tid]; qq += swarp[w][4 + tid]; }
        const float mean = ss * (1.f / (float)B_TOTAL);
        const float ex2  = qq * (1.f / (float)B_TOTAL);
        const float var  = fmaxf(ex2 - mean * mean, 0.f);
        const float inv  = rsqrtf(var + 1e-5f);
        const float sc   = gamma[tid] * inv;
        g_sb[tid]     = sc;
        g_sb[4 + tid] = beta[tid] - mean * sc;
    }
}

// ---- C: pure normalize, 1 float4 per thread --------------------------------
__global__ __launch_bounds__(256)
void qfc_kernelC(float* __restrict__ out)
{
    const float4 scv = *(const float4*)&g_sb[0];
    const float4 biv = *(const float4*)&g_sb[4];
    const int i = blockIdx.x * 256 + threadIdx.x;    // 65536 threads total
    float4 v = ((float4*)out)[i];
    v.x = v.x * scv.x + biv.x;
    v.y = v.y * scv.y + biv.y;
    v.z = v.z * scv.z + biv.z;
    v.w = v.w * scv.w + biv.w;
    ((float4*)out)[i] = v;
}

extern "C" void kernel_launch(void* const* d_in, const int* in_sizes, int n_in,
                              void* d_out, int out_size)
{
    const float* x      = (const float*)d_in[0];   // [65536,1,24,24]
    const float* params = (const float*)d_in[1];   // [4,2]
    const float* gamma  = (const float*)d_in[2];   // [4]
    const float* beta   = (const float*)d_in[3];   // [4]
    float* out = (float*)d_out;                    // [65536,4]

    qfc_kernelA<<<NB, THREADS>>>(x, params, out);
    qfc_kernelS<<<1, 256>>>(gamma, beta);
    qfc_kernelC<<<B_TOTAL / 256, 256>>>(out);
}